// round 8
// baseline (speedup 1.0000x reference)
#include <cuda_runtime.h>
#include <math.h>

// Problem constants
#define HH 1536
#define WW 1536
#define GXN (WW / 4)            // 384 float4 groups per row
#define NPIX (HH * WW)          // per-channel pixels
#define NP (10 * HH * WW)       // phi elements

#define BX 32                   // groups per block in x (128 px)
#define BY 8                    // rows per block
#define NTHREADS (BX * BY)      // 256
#define GRIDX (GXN / BX)        // 12
#define GRIDY (HH / BY)         // 192
#define NBLK (GRIDX * GRIDY)    // 2304

// Per-block partial sums (channel-major). Fully overwritten every call.
__device__ float g_partial[10 * NBLK];
// Completion ticket. Static-zero at load; last block resets to 0 each launch.
__device__ unsigned int g_count;

// ---------------- acquire/release helpers (no L1-flushing fence!) ----------
__device__ __forceinline__ unsigned int ticket_acq_rel(unsigned int* p) {
    unsigned int old;
    asm volatile("atom.acq_rel.gpu.global.add.u32 %0, [%1], 1;"
                 : "=r"(old) : "l"(p) : "memory");
    return old;
}
__device__ __forceinline__ float ld_acquire(const float* p) {
    float v;
    asm volatile("ld.acquire.gpu.global.f32 %0, [%1];" : "=f"(v) : "l"(p) : "memory");
    return v;
}

// ---------------- float4 helpers ----------------
__device__ __forceinline__ float4 mk4(float a, float b, float c, float d) {
    return make_float4(a, b, c, d);
}
__device__ __forceinline__ float4 operator+(const float4& a, const float4& b) {
    return mk4(a.x + b.x, a.y + b.y, a.z + b.z, a.w + b.w);
}
__device__ __forceinline__ float4 operator-(const float4& a, const float4& b) {
    return mk4(a.x - b.x, a.y - b.y, a.z - b.z, a.w - b.w);
}
__device__ __forceinline__ float4 operator*(float s, const float4& a) {
    return mk4(s * a.x, s * a.y, s * a.z, s * a.w);
}
__device__ __forceinline__ float4& operator+=(float4& a, const float4& b) {
    a.x += b.x; a.y += b.y; a.z += b.z; a.w += b.w; return a;
}
// x-shift permutes: value at x-1 / x+1 / x-2 / x+2 for the 4-lane group
__device__ __forceinline__ float4 shl1(const float4& L, const float4& C) {
    return mk4(L.w, C.x, C.y, C.z);
}
__device__ __forceinline__ float4 shr1(const float4& C, const float4& R) {
    return mk4(C.y, C.z, C.w, R.x);
}
__device__ __forceinline__ float4 shl2(const float4& L, const float4& C) {
    return mk4(L.z, L.w, C.x, C.y);
}
__device__ __forceinline__ float4 shr2(const float4& C, const float4& R) {
    return mk4(C.z, C.w, R.x, R.y);
}
__device__ __forceinline__ float4 clamp4(const float4& a, float lo, float hi) {
    return mk4(fminf(fmaxf(a.x, lo), hi), fminf(fmaxf(a.y, lo), hi),
               fminf(fmaxf(a.z, lo), hi), fminf(fmaxf(a.w, lo), hi));
}
__device__ __forceinline__ float4 fabs4(const float4& a) {
    return mk4(fabsf(a.x), fabsf(a.y), fabsf(a.z), fabsf(a.w));
}

// Per-channel reaction term (c becomes compile-time after full unroll)
__device__ __forceinline__ float react(int c, float p, float lap, float bil,
                                        float g, float a0) {
    float p2 = p * p;
    float p3 = p2 * p;
    switch (c) {
        case 0: return -g * lap - a0 * p3 + 0.12f * bil;
        case 1: return -g * lap + 0.15f * __sinf(p) + 0.08f * p3;
        case 2: return -g * lap + 0.2f * p * (1.0f - p2);
        case 3: return -g * lap - 0.03f * p3 * p2 + 0.08f * bil;
        case 4: return -g * lap + 0.12f * p * __logf(fabsf(p) + 1e-6f) + 0.02f * bil;
        case 5: return -g * lap + 0.08f * p3 - 0.02f * p3 * p2;
        case 6: return -g * lap + 0.06f * p2 * p2 - 0.04f * p;
        case 7: {
            float pc = fminf(fmaxf(p, -2.0f), 2.0f);
            float e = __expf(pc);
            return -g * lap + 0.08f * (0.5f * (e - 1.0f / e));
        }
        case 8: return -g * lap + 0.05f * p2 - 0.08f * p;
        case 9: return -g * lap + 0.02f * p3 * p3 - 0.04f * p3 + 0.01f * bil;
    }
    return 0.0f;
}

__global__ void __launch_bounds__(NTHREADS, 2)
step_kernel(const float* __restrict__ phi,
            const float* __restrict__ sens,
            const float* __restrict__ gam,
            const float* __restrict__ alp,
            const float* __restrict__ mixw,
            float* __restrict__ out) {
    __shared__ float sw[100];
    __shared__ float sg[10];
    __shared__ float sred[NTHREADS / 32][10];
    __shared__ unsigned int s_ticket;
    __shared__ double dred[NTHREADS / 32];

    const int tid = threadIdx.x;
    if (tid < 100) sw[tid] = mixw[tid];
    if (tid < 10) sg[tid] = gam[tid];
    const float a0 = alp[0];
    __syncthreads();

    // 2D decomposition: warp = one 32-group row segment, 8 rows per block.
    const int tx = tid & (BX - 1);
    const int ty = tid >> 5;
    const int gx = blockIdx.x * BX + tx;
    const int y  = blockIdx.y * BY + ty;

    // Periodic wrap indices
    const int ym1 = y ? y - 1 : HH - 1;
    const int yp1 = (y == HH - 1) ? 0 : y + 1;
    const int ym2 = (y >= 2) ? y - 2 : y + HH - 2;
    const int yp2 = (y < HH - 2) ? y + 2 : y + 2 - HH;
    const int gxm1 = gx ? gx - 1 : GXN - 1;
    const int gxp1 = (gx == GXN - 1) ? 0 : gx + 1;

    const float4* __restrict__ P = reinterpret_cast<const float4*>(phi);
    float4* __restrict__ O = reinterpret_cast<float4*>(out);

    // Load all channel centers (kept in registers for coupling/means)
    float4 cen[10];
#pragma unroll
    for (int c = 0; c < 10; c++) {
        cen[c] = P[(c * HH + y) * GXN + gx];
    }

    const float4 fm = 0.2f * (cen[0] + cen[1] + cen[2] + cen[3] + cen[4]);
    const float4 sm = 0.2f * (cen[5] + cen[6] + cen[7] + cen[8] + cen[9]);
    const float4 sd = reinterpret_cast<const float4*>(sens)[y * GXN + gx];
    const float4 asd = fabs4(sd);

    float chsum[10];

#pragma unroll
    for (int c = 0; c < 10; c++) {
        const int pb = c * HH;
        const float4 C = cen[c];
        const float4 uC = P[(pb + ym1) * GXN + gx];
        const float4 dC = P[(pb + yp1) * GXN + gx];
        const float4 L = P[(pb + y) * GXN + gxm1];
        const float4 R = P[(pb + y) * GXN + gxp1];
        const float4 sl = shl1(L, C);
        const float4 sr = shr1(C, R);
        const float4 s4 = uC + dC + sl + sr;
        const float4 lap = s4 - 4.0f * C;

        float4 bil = mk4(0.f, 0.f, 0.f, 0.f);
        const bool needB = (c == 0 || c == 3 || c == 4 || c == 9);
        if (needB) {
            const float4 uL = P[(pb + ym1) * GXN + gxm1];
            const float4 uR = P[(pb + ym1) * GXN + gxp1];
            const float4 dL = P[(pb + yp1) * GXN + gxm1];
            const float4 dR = P[(pb + yp1) * GXN + gxp1];
            const float4 uu = P[(pb + ym2) * GXN + gx];
            const float4 dd = P[(pb + yp2) * GXN + gx];
            const float4 diag = shl1(uL, uC) + shr1(uC, uR) + shl1(dL, dC) + shr1(dC, dR);
            const float4 ring2 = uu + dd + shl2(L, C) + shr2(C, R);
            bil = 20.0f * C - 8.0f * s4 + 2.0f * diag + ring2;
        }

        const float gc = sg[c];
        float4 dv;
        dv.x = react(c, C.x, lap.x, bil.x, gc, a0);
        dv.y = react(c, C.y, lap.y, bil.y, gc, a0);
        dv.z = react(c, C.z, lap.z, bil.z, gc, a0);
        dv.w = react(c, C.w, lap.w, bil.w, gc, a0);

        // Channel coupling: mix_w[c,:] . cen[:]
        float4 coup = mk4(0.f, 0.f, 0.f, 0.f);
#pragma unroll
        for (int k = 0; k < 10; k++) {
            const float w = sw[c * 10 + k];
            coup += w * cen[k];
        }

        float dtc;
        if (c < 5) {
            dv += 0.06f * coup;   // EPS_FAST
            dv += 0.02f * sm;     // S2F * slow_mean
            dtc = 0.02f;          // DT * FAST_DT
        } else {
            dv += 0.02f * coup;   // EPS_SLOW
            dv += 0.04f * fm;     // F2S * fast_mean
            dtc = 0.004f;         // DT * SLOW_DT
        }
        if (c == 0) dv += 0.2f * sd;
        if (c == 4) dv += 0.08f * asd;
        if (c == 9) dv += 0.05f * sd;

        const float4 r = clamp4(C + dtc * dv, -4.0f, 4.0f);
        O[(pb + y) * GXN + gx] = r;
        chsum[c] = r.x + r.y + r.z + r.w;
    }

    // Block reduction of channel sums -> per-block partials (plain stores)
    const int lane = tid & 31;
    const int wrp = tid >> 5;
#pragma unroll
    for (int c = 0; c < 10; c++) {
        float v = chsum[c];
#pragma unroll
        for (int off = 16; off; off >>= 1)
            v += __shfl_down_sync(0xffffffffu, v, off);
        if (lane == 0) sred[wrp][c] = v;
    }
    __syncthreads();
    const int bid = blockIdx.y * GRIDX + blockIdx.x;
    if (tid < 10) {
        float s = 0.0f;
#pragma unroll
        for (int w2 = 0; w2 < NTHREADS / 32; w2++) s += sred[w2][tid];
        g_partial[tid * NBLK + bid] = s;
    }
    __syncthreads();   // partial stores ordered before tid0's release-atomic

    // --- Fence-free fused finalize: acq_rel ticket, acquire loads.        ---
    // No __threadfence() => no CCTL.IVALL L1 flush (the R5 disaster).
    if (tid == 0) s_ticket = ticket_acq_rel(&g_count);
    __syncthreads();
    if (s_ticket == NBLK - 1) {
        // Last block: all other blocks' partials are published (release via
        // their acq_rel ticket adds; our add acquired the final value).
#pragma unroll
        for (int c = 0; c < 10; c++) {
            double acc = 0.0;
            for (int i = tid; i < NBLK; i += NTHREADS)
                acc += (double)ld_acquire(&g_partial[c * NBLK + i]);
#pragma unroll
            for (int off = 16; off; off >>= 1)
                acc += __shfl_down_sync(0xffffffffu, acc, off);
            if (lane == 0) dred[wrp] = acc;
            __syncthreads();
            if (tid == 0) {
                double t = 0.0;
#pragma unroll
                for (int w2 = 0; w2 < NTHREADS / 32; w2++) t += dred[w2];
                const float m = (float)(t / (double)NPIX);
                out[NP + 2 + c] = m;          // field_means[c]
                if (c == 0) out[NP] = m;      // phi1_mean
                if (c == 4) out[NP + 1] = m;  // phi5_mean
            }
            __syncthreads();
        }
        if (tid == 0) g_count = 0;  // reset for next graph replay
    }
}

extern "C" void kernel_launch(void* const* d_in, const int* in_sizes, int n_in,
                              void* d_out, int out_size) {
    const float* phi  = (const float*)d_in[0];
    const float* sens = (const float*)d_in[1];
    const float* gam  = (const float*)d_in[2];
    const float* alp  = (const float*)d_in[3];
    const float* mixw = (const float*)d_in[4];
    float* out = (float*)d_out;

    dim3 grid(GRIDX, GRIDY);
    step_kernel<<<grid, NTHREADS>>>(phi, sens, gam, alp, mixw, out);
}

// round 9
// speedup vs baseline: 1.9778x; 1.9778x over previous
#include <cuda_runtime.h>
#include <math.h>

// Problem constants
#define HH 1536
#define WW 1536
#define GXN (WW / 4)            // 384 float4 groups per row
#define NPIX (HH * WW)          // per-channel pixels
#define NP (10 * HH * WW)       // phi elements

#define BX 32                   // groups per block in x (128 px)
#define BY 8                    // rows per block
#define NTHREADS (BX * BY)      // 256
#define GRIDX (GXN / BX)        // 12
#define GRIDY (HH / BY)         // 192
#define NBLK (GRIDX * GRIDY)    // 2304

// Per-block partial sums (channel-major). Fully overwritten every call.
__device__ float g_partial[10 * NBLK];

// ---------------- float4 helpers ----------------
__device__ __forceinline__ float4 mk4(float a, float b, float c, float d) {
    return make_float4(a, b, c, d);
}
__device__ __forceinline__ float4 operator+(const float4& a, const float4& b) {
    return mk4(a.x + b.x, a.y + b.y, a.z + b.z, a.w + b.w);
}
__device__ __forceinline__ float4 operator-(const float4& a, const float4& b) {
    return mk4(a.x - b.x, a.y - b.y, a.z - b.z, a.w - b.w);
}
__device__ __forceinline__ float4 operator*(float s, const float4& a) {
    return mk4(s * a.x, s * a.y, s * a.z, s * a.w);
}
__device__ __forceinline__ float4& operator+=(float4& a, const float4& b) {
    a.x += b.x; a.y += b.y; a.z += b.z; a.w += b.w; return a;
}
// x-shift permutes: value at x-1 / x+1 / x-2 / x+2 for the 4-lane group
__device__ __forceinline__ float4 shl1(const float4& L, const float4& C) {
    return mk4(L.w, C.x, C.y, C.z);
}
__device__ __forceinline__ float4 shr1(const float4& C, const float4& R) {
    return mk4(C.y, C.z, C.w, R.x);
}
__device__ __forceinline__ float4 shl2(const float4& L, const float4& C) {
    return mk4(L.z, L.w, C.x, C.y);
}
__device__ __forceinline__ float4 shr2(const float4& C, const float4& R) {
    return mk4(C.z, C.w, R.x, R.y);
}
__device__ __forceinline__ float4 clamp4(const float4& a, float lo, float hi) {
    return mk4(fminf(fmaxf(a.x, lo), hi), fminf(fmaxf(a.y, lo), hi),
               fminf(fmaxf(a.z, lo), hi), fminf(fmaxf(a.w, lo), hi));
}
__device__ __forceinline__ float4 fabs4(const float4& a) {
    return mk4(fabsf(a.x), fabsf(a.y), fabsf(a.z), fabsf(a.w));
}

// Per-channel reaction term (c becomes compile-time after full unroll)
__device__ __forceinline__ float react(int c, float p, float lap, float bil,
                                        float g, float a0) {
    float p2 = p * p;
    float p3 = p2 * p;
    switch (c) {
        case 0: return -g * lap - a0 * p3 + 0.12f * bil;
        case 1: return -g * lap + 0.15f * __sinf(p) + 0.08f * p3;
        case 2: return -g * lap + 0.2f * p * (1.0f - p2);
        case 3: return -g * lap - 0.03f * p3 * p2 + 0.08f * bil;
        case 4: return -g * lap + 0.12f * p * __logf(fabsf(p) + 1e-6f) + 0.02f * bil;
        case 5: return -g * lap + 0.08f * p3 - 0.02f * p3 * p2;
        case 6: return -g * lap + 0.06f * p2 * p2 - 0.04f * p;
        case 7: {
            float pc = fminf(fmaxf(p, -2.0f), 2.0f);
            float e = __expf(pc);
            return -g * lap + 0.08f * (0.5f * (e - 1.0f / e));
        }
        case 8: return -g * lap + 0.05f * p2 - 0.08f * p;
        case 9: return -g * lap + 0.02f * p3 * p3 - 0.04f * p3 + 0.01f * bil;
    }
    return 0.0f;
}

__global__ void __launch_bounds__(NTHREADS, 3)
step_kernel(const float* __restrict__ phi,
            const float* __restrict__ sens,
            const float* __restrict__ gam,
            const float* __restrict__ alp,
            const float* __restrict__ mixw,
            float* __restrict__ out) {
    __shared__ float sw[100];                 // effective coupling matrix
    __shared__ float sg[10];
    __shared__ float sred[NTHREADS / 32][10];

    const int tid = threadIdx.x;
    if (tid < 100) {
        const int c = tid / 10;
        const int k = tid - c * 10;
        // eps*mix_w with rank-1 cross-mean terms folded in:
        // c<5 : + S2F*0.2 on slow k;  c>=5 : + F2S*0.2 on fast k.
        float w = mixw[tid] * ((c < 5) ? 0.06f : 0.02f);
        if (c < 5) { if (k >= 5) w += 0.004f; }   // 0.02 * 0.2
        else       { if (k < 5)  w += 0.008f; }   // 0.04 * 0.2
        sw[tid] = w;
    }
    if (tid < 10) sg[tid] = gam[tid];
    const float a0 = alp[0];
    __syncthreads();

    // 2D decomposition: warp = one 32-group row segment, 8 rows per block.
    const int tx = tid & (BX - 1);
    const int ty = tid >> 5;
    const int gx = blockIdx.x * BX + tx;
    const int y  = blockIdx.y * BY + ty;

    // Periodic wrap indices
    const int ym1 = y ? y - 1 : HH - 1;
    const int yp1 = (y == HH - 1) ? 0 : y + 1;
    const int ym2 = (y >= 2) ? y - 2 : y + HH - 2;
    const int yp2 = (y < HH - 2) ? y + 2 : y + 2 - HH;
    const int gxm1 = gx ? gx - 1 : GXN - 1;
    const int gxp1 = (gx == GXN - 1) ? 0 : gx + 1;

    const float4* __restrict__ P = reinterpret_cast<const float4*>(phi);
    float4* __restrict__ O = reinterpret_cast<float4*>(out);

    // ---- Phase 1: stream centers once, build coupling accumulators ----
    float4 coup[10];
#pragma unroll
    for (int c = 0; c < 10; c++) coup[c] = mk4(0.f, 0.f, 0.f, 0.f);
#pragma unroll
    for (int k = 0; k < 10; k++) {
        const float4 t = P[(k * HH + y) * GXN + gx];
#pragma unroll
        for (int c = 0; c < 10; c++) {
            coup[c] += sw[c * 10 + k] * t;
        }
    }

    const float4 sd = reinterpret_cast<const float4*>(sens)[y * GXN + gx];
    const float4 asd = fabs4(sd);

    const int lane = tid & 31;
    const int wrp = tid >> 5;

    // ---- Phase 2: per-channel stencil + update (centers re-hit L1) ----
#pragma unroll
    for (int c = 0; c < 10; c++) {
        const int pb = c * HH;
        const float4 C = P[(pb + y) * GXN + gx];   // L1 hit (phase-1 load)
        const float4 uC = P[(pb + ym1) * GXN + gx];
        const float4 dC = P[(pb + yp1) * GXN + gx];
        const float4 L = P[(pb + y) * GXN + gxm1];
        const float4 R = P[(pb + y) * GXN + gxp1];
        const float4 sl = shl1(L, C);
        const float4 sr = shr1(C, R);
        const float4 s4 = uC + dC + sl + sr;
        const float4 lap = s4 - 4.0f * C;

        float4 bil = mk4(0.f, 0.f, 0.f, 0.f);
        const bool needB = (c == 0 || c == 3 || c == 4 || c == 9);
        if (needB) {
            const float4 uL = P[(pb + ym1) * GXN + gxm1];
            const float4 uR = P[(pb + ym1) * GXN + gxp1];
            const float4 dL = P[(pb + yp1) * GXN + gxm1];
            const float4 dR = P[(pb + yp1) * GXN + gxp1];
            const float4 uu = P[(pb + ym2) * GXN + gx];
            const float4 dd = P[(pb + yp2) * GXN + gx];
            const float4 diag = shl1(uL, uC) + shr1(uC, uR) + shl1(dL, dC) + shr1(dC, dR);
            const float4 ring2 = uu + dd + shl2(L, C) + shr2(C, R);
            bil = 20.0f * C - 8.0f * s4 + 2.0f * diag + ring2;
        }

        const float gc = sg[c];
        float4 dv;
        dv.x = react(c, C.x, lap.x, bil.x, gc, a0);
        dv.y = react(c, C.y, lap.y, bil.y, gc, a0);
        dv.z = react(c, C.z, lap.z, bil.z, gc, a0);
        dv.w = react(c, C.w, lap.w, bil.w, gc, a0);

        dv += coup[c];   // coupling + folded cross-mean terms

        const float dtc = (c < 5) ? 0.02f : 0.004f;  // DT * {FAST,SLOW}_DT
        if (c == 0) dv += 0.2f * sd;
        if (c == 4) dv += 0.08f * asd;
        if (c == 9) dv += 0.05f * sd;

        const float4 r = clamp4(C + dtc * dv, -4.0f, 4.0f);
        O[(pb + y) * GXN + gx] = r;

        // Per-iteration warp reduction of this channel's sum (frees chsum regs)
        float v = r.x + r.y + r.z + r.w;
#pragma unroll
        for (int off = 16; off; off >>= 1)
            v += __shfl_down_sync(0xffffffffu, v, off);
        if (lane == 0) sred[wrp][c] = v;
    }

    __syncthreads();
    if (tid < 10) {
        float s = 0.0f;
#pragma unroll
        for (int w2 = 0; w2 < NTHREADS / 32; w2++) s += sred[w2][tid];
        const int bid = blockIdx.y * GRIDX + blockIdx.x;
        g_partial[tid * NBLK + bid] = s;
    }
}

// One block per channel: parallel reduction of the 2304 per-block partials.
// Fixed reduction order -> deterministic across replays.
__global__ void __launch_bounds__(256, 1)
finalize_kernel(float* __restrict__ out) {
    __shared__ double sredd[256 / 32];
    const int c = blockIdx.x;
    const int tid = threadIdx.x;
    const int lane = tid & 31;
    const int wrp = tid >> 5;

    double acc = 0.0;
#pragma unroll
    for (int i = tid; i < NBLK; i += 256)
        acc += (double)g_partial[c * NBLK + i];
#pragma unroll
    for (int off = 16; off; off >>= 1)
        acc += __shfl_down_sync(0xffffffffu, acc, off);
    if (lane == 0) sredd[wrp] = acc;
    __syncthreads();
    if (tid == 0) {
        double t = 0.0;
#pragma unroll
        for (int w2 = 0; w2 < 8; w2++) t += sredd[w2];
        const float m = (float)(t / (double)NPIX);
        out[NP + 2 + c] = m;          // field_means[c]
        if (c == 0) out[NP] = m;      // phi1_mean
        if (c == 4) out[NP + 1] = m;  // phi5_mean
    }
}

extern "C" void kernel_launch(void* const* d_in, const int* in_sizes, int n_in,
                              void* d_out, int out_size) {
    const float* phi  = (const float*)d_in[0];
    const float* sens = (const float*)d_in[1];
    const float* gam  = (const float*)d_in[2];
    const float* alp  = (const float*)d_in[3];
    const float* mixw = (const float*)d_in[4];
    float* out = (float*)d_out;

    dim3 grid(GRIDX, GRIDY);
    step_kernel<<<grid, NTHREADS>>>(phi, sens, gam, alp, mixw, out);
    finalize_kernel<<<10, 256>>>(out);
}

// round 11
// speedup vs baseline: 2.5159x; 1.2721x over previous
#include <cuda_runtime.h>
#include <math.h>

// Problem constants
#define HH 1536
#define WW 1536
#define GXN (WW / 4)            // 384 float4 groups per row
#define NPIX (HH * WW)          // per-channel pixels
#define NP (10 * HH * WW)       // phi elements

#define BX 32                   // groups per block in x (128 px)
#define BY 8                    // rows per block
#define NTHREADS (BX * BY)      // 256
#define GRIDX (GXN / BX)        // 12
#define GRIDY (HH / BY)         // 192
#define NBLK (GRIDX * GRIDY)    // 2304

// Per-block partial sums (channel-major). Fully overwritten every call.
__device__ float g_partial[10 * NBLK];

// ---------------- float4 helpers ----------------
__device__ __forceinline__ float4 mk4(float a, float b, float c, float d) {
    return make_float4(a, b, c, d);
}
__device__ __forceinline__ float4 operator+(const float4& a, const float4& b) {
    return mk4(a.x + b.x, a.y + b.y, a.z + b.z, a.w + b.w);
}
__device__ __forceinline__ float4 operator-(const float4& a, const float4& b) {
    return mk4(a.x - b.x, a.y - b.y, a.z - b.z, a.w - b.w);
}
__device__ __forceinline__ float4 operator*(float s, const float4& a) {
    return mk4(s * a.x, s * a.y, s * a.z, s * a.w);
}
__device__ __forceinline__ float4& operator+=(float4& a, const float4& b) {
    a.x += b.x; a.y += b.y; a.z += b.z; a.w += b.w; return a;
}
// x-shift permutes: value at x-1 / x+1 / x-2 / x+2 for the 4-lane group
__device__ __forceinline__ float4 shl1(const float4& L, const float4& C) {
    return mk4(L.w, C.x, C.y, C.z);
}
__device__ __forceinline__ float4 shr1(const float4& C, const float4& R) {
    return mk4(C.y, C.z, C.w, R.x);
}
__device__ __forceinline__ float4 shl2(const float4& L, const float4& C) {
    return mk4(L.z, L.w, C.x, C.y);
}
__device__ __forceinline__ float4 shr2(const float4& C, const float4& R) {
    return mk4(C.z, C.w, R.x, R.y);
}
__device__ __forceinline__ float4 clamp4(const float4& a, float lo, float hi) {
    return mk4(fminf(fmaxf(a.x, lo), hi), fminf(fmaxf(a.y, lo), hi),
               fminf(fmaxf(a.z, lo), hi), fminf(fmaxf(a.w, lo), hi));
}
__device__ __forceinline__ float4 fabs4(const float4& a) {
    return mk4(fabsf(a.x), fabsf(a.y), fabsf(a.z), fabsf(a.w));
}

// Per-channel reaction term with dt (0.02 fast / 0.004 slow) pre-folded into
// every coefficient. g and a0 arrive pre-scaled by dt. (Validated in R6.)
__device__ __forceinline__ float react(int c, float p, float lap, float bil,
                                        float g, float a0) {
    float p2 = p * p;
    float p3 = p2 * p;
    switch (c) {
        case 0: return -g * lap - a0 * p3 + 0.0024f * bil;
        case 1: return -g * lap + 0.003f * __sinf(p) + 0.0016f * p3;
        case 2: return -g * lap + 0.004f * p * (1.0f - p2);
        case 3: return -g * lap - 0.0006f * p3 * p2 + 0.0016f * bil;
        case 4: return -g * lap + 0.0024f * p * __logf(fabsf(p) + 1e-6f) + 0.0004f * bil;
        case 5: return -g * lap + 0.00032f * p3 - 0.00008f * p3 * p2;
        case 6: return -g * lap + 0.00024f * p2 * p2 - 0.00016f * p;
        case 7: {
            float pc = fminf(fmaxf(p, -2.0f), 2.0f);
            float e = __expf(pc);
            return -g * lap + 0.00016f * (e - 1.0f / e);
        }
        case 8: return -g * lap + 0.0002f * p2 - 0.00032f * p;
        case 9: return -g * lap + 0.00008f * p3 * p3 - 0.00016f * p3 + 0.00004f * bil;
    }
    return 0.0f;
}

__global__ void __launch_bounds__(NTHREADS, 2)
step_kernel(const float* __restrict__ phi,
            const float* __restrict__ sens,
            const float* __restrict__ gam,
            const float* __restrict__ alp,
            const float* __restrict__ mixw,
            float* __restrict__ out) {
    __shared__ float sw[100];                 // effective coupling matrix
    __shared__ float sg[10];                  // dt * gamma
    __shared__ float sred[NTHREADS / 32][10];

    const int tid = threadIdx.x;
    if (tid < 100) {
        const int c = tid / 10;
        const int k = tid - c * 10;
        // dt*eps*mix_w with dt-scaled rank-1 cross-mean terms folded in.
        float w = mixw[tid] * ((c < 5) ? 0.0012f : 0.00008f);
        if (c < 5) { if (k >= 5) w += 0.00008f; }   // dt_f * S2F * 0.2
        else       { if (k < 5)  w += 0.000032f; }  // dt_s * F2S * 0.2
        sw[tid] = w;
    }
    if (tid < 10) sg[tid] = ((tid < 5) ? 0.02f : 0.004f) * gam[tid];
    const float a0 = 0.02f * alp[0];
    __syncthreads();

    // 2D decomposition: warp = one 32-group row segment, 8 rows per block.
    const int tx = tid & (BX - 1);
    const int ty = tid >> 5;
    const int gx = blockIdx.x * BX + tx;
    const int y  = blockIdx.y * BY + ty;

    // Periodic wrap indices
    const int ym1 = y ? y - 1 : HH - 1;
    const int yp1 = (y == HH - 1) ? 0 : y + 1;
    const int ym2 = (y >= 2) ? y - 2 : y + HH - 2;
    const int yp2 = (y < HH - 2) ? y + 2 : y + 2 - HH;
    const int gxm1 = gx ? gx - 1 : GXN - 1;
    const int gxp1 = (gx == GXN - 1) ? 0 : gx + 1;

    const float4* __restrict__ P = reinterpret_cast<const float4*>(phi);
    float4* __restrict__ O = reinterpret_cast<float4*>(out);

    // Load all channel centers (kept in registers for coupling)
    float4 cen[10];
#pragma unroll
    for (int c = 0; c < 10; c++) {
        cen[c] = P[(c * HH + y) * GXN + gx];
    }

    const float4 sd = reinterpret_cast<const float4*>(sens)[y * GXN + gx];
    const float4 asd = fabs4(sd);

    float chsum[10];

#pragma unroll
    for (int c = 0; c < 10; c++) {
        const int pb = c * HH;
        const float4 C = cen[c];
        const float4 uC = P[(pb + ym1) * GXN + gx];
        const float4 dC = P[(pb + yp1) * GXN + gx];
        const float4 L = P[(pb + y) * GXN + gxm1];
        const float4 R = P[(pb + y) * GXN + gxp1];
        const float4 sl = shl1(L, C);
        const float4 sr = shr1(C, R);
        const float4 s4 = uC + dC + sl + sr;
        const float4 lap = s4 - 4.0f * C;

        float4 bil = mk4(0.f, 0.f, 0.f, 0.f);
        const bool needB = (c == 0 || c == 3 || c == 4 || c == 9);
        if (needB) {
            const float4 uL = P[(pb + ym1) * GXN + gxm1];
            const float4 uR = P[(pb + ym1) * GXN + gxp1];
            const float4 dL = P[(pb + yp1) * GXN + gxm1];
            const float4 dR = P[(pb + yp1) * GXN + gxp1];
            const float4 uu = P[(pb + ym2) * GXN + gx];
            const float4 dd = P[(pb + yp2) * GXN + gx];
            const float4 diag = shl1(uL, uC) + shr1(uC, uR) + shl1(dL, dC) + shr1(dC, dR);
            const float4 ring2 = uu + dd + shl2(L, C) + shr2(C, R);
            bil = 20.0f * C - 8.0f * s4 + 2.0f * diag + ring2;
        }

        const float gc = sg[c];
        float4 dv;
        dv.x = react(c, C.x, lap.x, bil.x, gc, a0);
        dv.y = react(c, C.y, lap.y, bil.y, gc, a0);
        dv.z = react(c, C.z, lap.z, bil.z, gc, a0);
        dv.w = react(c, C.w, lap.w, bil.w, gc, a0);

        // Channel coupling: (effective M)[c,:] . cen[:]  (dt/eps/rank-1 folded)
#pragma unroll
        for (int k = 0; k < 10; k++) {
            const float w = sw[c * 10 + k];
            dv += w * cen[k];
        }

        // Folded sensory terms (dt pre-applied)
        if (c == 0) dv += 0.004f * sd;
        if (c == 4) dv += 0.0016f * asd;
        if (c == 9) dv += 0.0002f * sd;

        const float4 r = clamp4(C + dv, -4.0f, 4.0f);
        O[(pb + y) * GXN + gx] = r;
        chsum[c] = r.x + r.y + r.z + r.w;
    }

    // Block reduction of channel sums -> per-block partials (plain stores)
    const int lane = tid & 31;
    const int wrp = tid >> 5;
#pragma unroll
    for (int c = 0; c < 10; c++) {
        float v = chsum[c];
#pragma unroll
        for (int off = 16; off; off >>= 1)
            v += __shfl_down_sync(0xffffffffu, v, off);
        if (lane == 0) sred[wrp][c] = v;
    }
    __syncthreads();
    if (tid < 10) {
        float s = 0.0f;
#pragma unroll
        for (int w2 = 0; w2 < NTHREADS / 32; w2++) s += sred[w2][tid];
        const int bid = blockIdx.y * GRIDX + blockIdx.x;
        g_partial[tid * NBLK + bid] = s;
    }
}

// One block per channel: parallel reduction of the 2304 per-block partials.
// Fixed reduction order -> deterministic across replays.
__global__ void __launch_bounds__(256, 1)
finalize_kernel(float* __restrict__ out) {
    __shared__ double sredd[256 / 32];
    const int c = blockIdx.x;
    const int tid = threadIdx.x;
    const int lane = tid & 31;
    const int wrp = tid >> 5;

    double acc = 0.0;
#pragma unroll
    for (int i = tid; i < NBLK; i += 256)
        acc += (double)g_partial[c * NBLK + i];
#pragma unroll
    for (int off = 16; off; off >>= 1)
        acc += __shfl_down_sync(0xffffffffu, acc, off);
    if (lane == 0) sredd[wrp] = acc;
    __syncthreads();
    if (tid == 0) {
        double t = 0.0;
#pragma unroll
        for (int w2 = 0; w2 < 8; w2++) t += sredd[w2];
        const float m = (float)(t / (double)NPIX);
        out[NP + 2 + c] = m;          // field_means[c]
        if (c == 0) out[NP] = m;      // phi1_mean
        if (c == 4) out[NP + 1] = m;  // phi5_mean
    }
}

extern "C" void kernel_launch(void* const* d_in, const int* in_sizes, int n_in,
                              void* d_out, int out_size) {
    const float* phi  = (const float*)d_in[0];
    const float* sens = (const float*)d_in[1];
    const float* gam  = (const float*)d_in[2];
    const float* alp  = (const float*)d_in[3];
    const float* mixw = (const float*)d_in[4];
    float* out = (float*)d_out;

    dim3 grid(GRIDX, GRIDY);
    step_kernel<<<grid, NTHREADS>>>(phi, sens, gam, alp, mixw, out);
    finalize_kernel<<<10, 256>>>(out);
}

// round 12
// speedup vs baseline: 2.7263x; 1.0836x over previous
#include <cuda_runtime.h>
#include <cuda_fp16.h>
#include <math.h>

// Problem constants
#define HH 1536
#define WW 1536
#define GXN (WW / 4)            // 384 float4 groups per row
#define NPIX (HH * WW)          // per-channel pixels
#define NP (10 * HH * WW)       // phi elements

#define BX 32                   // groups per block in x (128 px)
#define BY 8                    // rows per block
#define NTHREADS (BX * BY)      // 256
#define GRIDX (GXN / BX)        // 12
#define GRIDY (HH / BY)         // 192
#define NBLK (GRIDX * GRIDY)    // 2304

// Per-block partial sums (channel-major). Fully overwritten every call.
__device__ float g_partial[10 * NBLK];

// ---------------- float4 helpers ----------------
__device__ __forceinline__ float4 mk4(float a, float b, float c, float d) {
    return make_float4(a, b, c, d);
}
__device__ __forceinline__ float4 operator+(const float4& a, const float4& b) {
    return mk4(a.x + b.x, a.y + b.y, a.z + b.z, a.w + b.w);
}
__device__ __forceinline__ float4 operator-(const float4& a, const float4& b) {
    return mk4(a.x - b.x, a.y - b.y, a.z - b.z, a.w - b.w);
}
__device__ __forceinline__ float4 operator*(float s, const float4& a) {
    return mk4(s * a.x, s * a.y, s * a.z, s * a.w);
}
__device__ __forceinline__ float4& operator+=(float4& a, const float4& b) {
    a.x += b.x; a.y += b.y; a.z += b.z; a.w += b.w; return a;
}
// x-shift permutes: value at x-1 / x+1 / x-2 / x+2 for the 4-lane group
__device__ __forceinline__ float4 shl1(const float4& L, const float4& C) {
    return mk4(L.w, C.x, C.y, C.z);
}
__device__ __forceinline__ float4 shr1(const float4& C, const float4& R) {
    return mk4(C.y, C.z, C.w, R.x);
}
__device__ __forceinline__ float4 shl2(const float4& L, const float4& C) {
    return mk4(L.z, L.w, C.x, C.y);
}
__device__ __forceinline__ float4 shr2(const float4& C, const float4& R) {
    return mk4(C.z, C.w, R.x, R.y);
}
__device__ __forceinline__ float4 clamp4(const float4& a, float lo, float hi) {
    return mk4(fminf(fmaxf(a.x, lo), hi), fminf(fmaxf(a.y, lo), hi),
               fminf(fmaxf(a.z, lo), hi), fminf(fmaxf(a.w, lo), hi));
}
__device__ __forceinline__ float4 fabs4(const float4& a) {
    return mk4(fabsf(a.x), fabsf(a.y), fabsf(a.z), fabsf(a.w));
}

// Per-channel reaction term with dt (0.02 fast / 0.004 slow) pre-folded into
// every coefficient. g and a0 arrive pre-scaled by dt. (Validated R6/R11.)
__device__ __forceinline__ float react(int c, float p, float lap, float bil,
                                        float g, float a0) {
    float p2 = p * p;
    float p3 = p2 * p;
    switch (c) {
        case 0: return -g * lap - a0 * p3 + 0.0024f * bil;
        case 1: return -g * lap + 0.003f * __sinf(p) + 0.0016f * p3;
        case 2: return -g * lap + 0.004f * p * (1.0f - p2);
        case 3: return -g * lap - 0.0006f * p3 * p2 + 0.0016f * bil;
        case 4: return -g * lap + 0.0024f * p * __logf(fabsf(p) + 1e-6f) + 0.0004f * bil;
        case 5: return -g * lap + 0.00032f * p3 - 0.00008f * p3 * p2;
        case 6: return -g * lap + 0.00024f * p2 * p2 - 0.00016f * p;
        case 7: {
            float pc = fminf(fmaxf(p, -2.0f), 2.0f);
            float e = __expf(pc);
            return -g * lap + 0.00016f * (e - 1.0f / e);
        }
        case 8: return -g * lap + 0.0002f * p2 - 0.00032f * p;
        case 9: return -g * lap + 0.00008f * p3 * p3 - 0.00016f * p3 + 0.00004f * bil;
    }
    return 0.0f;
}

__global__ void __launch_bounds__(NTHREADS, 2)
step_kernel(const float* __restrict__ phi,
            const float* __restrict__ sens,
            const float* __restrict__ gam,
            const float* __restrict__ alp,
            const float* __restrict__ mixw,
            float* __restrict__ out) {
    __shared__ __half2 sw2[100];              // effective coupling matrix (w,w)
    __shared__ float sg[10];                  // dt * gamma
    __shared__ float sred[NTHREADS / 32][10];

    const int tid = threadIdx.x;
    if (tid < 100) {
        const int c = tid / 10;
        const int k = tid - c * 10;
        // dt*eps*mix_w with dt-scaled rank-1 cross-mean terms folded in.
        float w = mixw[tid] * ((c < 5) ? 0.0012f : 0.00008f);
        if (c < 5) { if (k >= 5) w += 0.00008f; }   // dt_f * S2F * 0.2
        else       { if (k < 5)  w += 0.000032f; }  // dt_s * F2S * 0.2
        sw2[tid] = __float2half2_rn(w);
    }
    if (tid < 10) sg[tid] = ((tid < 5) ? 0.02f : 0.004f) * gam[tid];
    const float a0 = 0.02f * alp[0];
    __syncthreads();

    // 2D decomposition: warp = one 32-group row segment, 8 rows per block.
    const int tx = tid & (BX - 1);
    const int ty = tid >> 5;
    const int gx = blockIdx.x * BX + tx;
    const int y  = blockIdx.y * BY + ty;

    // Periodic wrap indices
    const int ym1 = y ? y - 1 : HH - 1;
    const int yp1 = (y == HH - 1) ? 0 : y + 1;
    const int ym2 = (y >= 2) ? y - 2 : y + HH - 2;
    const int yp2 = (y < HH - 2) ? y + 2 : y + 2 - HH;
    const int gxm1 = gx ? gx - 1 : GXN - 1;
    const int gxp1 = (gx == GXN - 1) ? 0 : gx + 1;

    const float4* __restrict__ P = reinterpret_cast<const float4*>(phi);
    float4* __restrict__ O = reinterpret_cast<float4*>(out);

    // Stream centers once, keep them as fp16 lane-pairs for the coupling.
    // (fp32 C is re-loaded per channel below -> guaranteed L1 hit.)
    __half2 cen_lo[10], cen_hi[10];
#pragma unroll
    for (int k = 0; k < 10; k++) {
        const float4 t = P[(k * HH + y) * GXN + gx];
        cen_lo[k] = __floats2half2_rn(t.x, t.y);
        cen_hi[k] = __floats2half2_rn(t.z, t.w);
    }

    const float4 sd = reinterpret_cast<const float4*>(sens)[y * GXN + gx];
    const float4 asd = fabs4(sd);

    float chsum[10];

#pragma unroll
    for (int c = 0; c < 10; c++) {
        const int pb = c * HH;
        const float4 C = P[(pb + y) * GXN + gx];    // L1 hit (streamed above)
        const float4 uC = P[(pb + ym1) * GXN + gx];
        const float4 dC = P[(pb + yp1) * GXN + gx];
        const float4 L = P[(pb + y) * GXN + gxm1];
        const float4 R = P[(pb + y) * GXN + gxp1];
        const float4 sl = shl1(L, C);
        const float4 sr = shr1(C, R);
        const float4 s4 = uC + dC + sl + sr;
        const float4 lap = s4 - 4.0f * C;

        float4 bil = mk4(0.f, 0.f, 0.f, 0.f);
        const bool needB = (c == 0 || c == 3 || c == 4 || c == 9);
        if (needB) {
            const float4 uL = P[(pb + ym1) * GXN + gxm1];
            const float4 uR = P[(pb + ym1) * GXN + gxp1];
            const float4 dL = P[(pb + yp1) * GXN + gxm1];
            const float4 dR = P[(pb + yp1) * GXN + gxp1];
            const float4 uu = P[(pb + ym2) * GXN + gx];
            const float4 dd = P[(pb + yp2) * GXN + gx];
            const float4 diag = shl1(uL, uC) + shr1(uC, uR) + shl1(dL, dC) + shr1(dC, dR);
            const float4 ring2 = uu + dd + shl2(L, C) + shr2(C, R);
            bil = 20.0f * C - 8.0f * s4 + 2.0f * diag + ring2;
        }

        const float gc = sg[c];
        float4 dv;
        dv.x = react(c, C.x, lap.x, bil.x, gc, a0);
        dv.y = react(c, C.y, lap.y, bil.y, gc, a0);
        dv.z = react(c, C.z, lap.z, bil.z, gc, a0);
        dv.w = react(c, C.w, lap.w, bil.w, gc, a0);

        // fp16 coupling: (effective M)[c,:] . cen[:]  via HFMA2 lane-pairs.
        __half2 alo = __hmul2(sw2[c * 10], cen_lo[0]);
        __half2 ahi = __hmul2(sw2[c * 10], cen_hi[0]);
#pragma unroll
        for (int k = 1; k < 10; k++) {
            const __half2 w2 = sw2[c * 10 + k];
            alo = __hfma2(w2, cen_lo[k], alo);
            ahi = __hfma2(w2, cen_hi[k], ahi);
        }
        const float2 plo = __half22float2(alo);
        const float2 phi2 = __half22float2(ahi);
        dv.x += plo.x; dv.y += plo.y; dv.z += phi2.x; dv.w += phi2.y;

        // Folded sensory terms (dt pre-applied)
        if (c == 0) dv += 0.004f * sd;
        if (c == 4) dv += 0.0016f * asd;
        if (c == 9) dv += 0.0002f * sd;

        const float4 r = clamp4(C + dv, -4.0f, 4.0f);
        O[(pb + y) * GXN + gx] = r;
        chsum[c] = r.x + r.y + r.z + r.w;
    }

    // Block reduction of channel sums -> per-block partials (plain stores)
    const int lane = tid & 31;
    const int wrp = tid >> 5;
#pragma unroll
    for (int c = 0; c < 10; c++) {
        float v = chsum[c];
#pragma unroll
        for (int off = 16; off; off >>= 1)
            v += __shfl_down_sync(0xffffffffu, v, off);
        if (lane == 0) sred[wrp][c] = v;
    }
    __syncthreads();
    if (tid < 10) {
        float s = 0.0f;
#pragma unroll
        for (int w2 = 0; w2 < NTHREADS / 32; w2++) s += sred[w2][tid];
        const int bid = blockIdx.y * GRIDX + blockIdx.x;
        g_partial[tid * NBLK + bid] = s;
    }
}

// One block per channel: parallel reduction of the 2304 per-block partials.
// Fixed reduction order -> deterministic across replays.
__global__ void __launch_bounds__(256, 1)
finalize_kernel(float* __restrict__ out) {
    __shared__ double sredd[256 / 32];
    const int c = blockIdx.x;
    const int tid = threadIdx.x;
    const int lane = tid & 31;
    const int wrp = tid >> 5;

    double acc = 0.0;
#pragma unroll
    for (int i = tid; i < NBLK; i += 256)
        acc += (double)g_partial[c * NBLK + i];
#pragma unroll
    for (int off = 16; off; off >>= 1)
        acc += __shfl_down_sync(0xffffffffu, acc, off);
    if (lane == 0) sredd[wrp] = acc;
    __syncthreads();
    if (tid == 0) {
        double t = 0.0;
#pragma unroll
        for (int w2 = 0; w2 < 8; w2++) t += sredd[w2];
        const float m = (float)(t / (double)NPIX);
        out[NP + 2 + c] = m;          // field_means[c]
        if (c == 0) out[NP] = m;      // phi1_mean
        if (c == 4) out[NP + 1] = m;  // phi5_mean
    }
}

extern "C" void kernel_launch(void* const* d_in, const int* in_sizes, int n_in,
                              void* d_out, int out_size) {
    const float* phi  = (const float*)d_in[0];
    const float* sens = (const float*)d_in[1];
    const float* gam  = (const float*)d_in[2];
    const float* alp  = (const float*)d_in[3];
    const float* mixw = (const float*)d_in[4];
    float* out = (float*)d_out;

    dim3 grid(GRIDX, GRIDY);
    step_kernel<<<grid, NTHREADS>>>(phi, sens, gam, alp, mixw, out);
    finalize_kernel<<<10, 256>>>(out);
}